// round 13
// baseline (speedup 1.0000x reference)
#include <cuda_runtime.h>
#include <math.h>

#define BN   512     // B*N
#define FEAT 384
#define FFN  768
#define ZD   384
#define HID  192
#define NB   4
#define NN   128
#define LN_EPS 1e-5f
#define NBLK 192
#define K1S  18      // k1 staging stride (16 rows + 2 pad, even)
#define K4S  10      // k4 staging stride (8 rows + 2 pad, even)

typedef unsigned long long ull;

// ---------------- scratch (device globals; no allocation) ----------------
__device__ __align__(16) float g_xh[BN * ZD];
__device__ __align__(16) float g_z[BN * ZD];
__device__ __align__(16) float g_c0[ZD];
__device__ __align__(16) float g_T[NB * ZD];
__device__ float g_diag[BN];
__device__ float g_off[BN];
__device__ float g_eo[BN];
__device__ float g_wd[BN];
__device__ float g_rD[BN];
// sw global barrier state (self-resetting; generation is monotonic)
__device__ int          g_barcnt = 0;
__device__ volatile int g_bargen = 0;

__device__ __forceinline__ float gelu_exact(float x) {
    return 0.5f * x * (1.0f + erff(x * 0.70710678118654752440f));
}
__device__ __forceinline__ ull dup2(float x) {
    ull r; asm("mov.b64 %0, {%1, %1};" : "=l"(r) : "f"(x)); return r;
}
__device__ __forceinline__ void fma2(ull &d, ull a, ull b) {
    asm("fma.rn.f32x2 %0, %1, %2, %0;" : "+l"(d) : "l"(a), "l"(b));
}
__device__ __forceinline__ float2 unp2(ull v) {
    float2 f; asm("mov.b64 {%0, %1}, %2;" : "=f"(f.x), "=f"(f.y) : "l"(v)); return f;
}

// all NBLK blocks arrive; counter resets each use; gen increments.
__device__ __forceinline__ void gbar() {
    __syncthreads();
    if (threadIdx.x == 0) {
        __threadfence();
        int gen = g_bargen;
        if (atomicAdd(&g_barcnt, 1) == NBLK - 1) {
            g_barcnt = 0;
            __threadfence();
            g_bargen = gen + 1;
        } else {
            while (g_bargen == gen) { __nanosleep(64); }
        }
        __threadfence();
    }
    __syncthreads();
}

__global__ __launch_bounds__(256, 2)
void fused_all(const float* __restrict__ x,
               const float* __restrict__ U_w,
               const float* __restrict__ U_b,
               const float* __restrict__ ln_w,
               const float* __restrict__ ln_b,
               const float* __restrict__ enc_w,
               const float* __restrict__ enc_b,
               const float* __restrict__ dec_w,
               const float* __restrict__ dec_b,
               const float* __restrict__ V_w,
               const float* __restrict__ V_b,
               float* __restrict__ out) {
    __shared__ float sm[8192];            // 32 KB, reused every phase
    __shared__ float rs1[4][8], rs2[4][8], mu_s[4], rsd_s[4];
    __shared__ float redd[4][8], redo[4][8], red[5], eo_s[NN], wds[8], rds[8];

    const int t    = threadIdx.x;
    const int bid  = blockIdx.x;
    const int wid  = t >> 5, lane = t & 31;

    // ================= phase 1: k1 GEMM (+ distributed c0) =================
    // c0[o] = gelu(enc_b) @ dec_w + dec_b; block bid computes o = 2bid, 2bid+1
    if (wid < 2) {
        int o = 2 * bid + wid;
        float acc = 0.f;
        for (int u = lane; u < HID; u += 32)
            acc += gelu_exact(enc_b[u]) * dec_w[(size_t)u * ZD + o];
#pragma unroll
        for (int s = 16; s > 0; s >>= 1) acc += __shfl_down_sync(0xffffffffu, acc, s);
        if (lane == 0) g_c0[o] = acc + dec_b[o];
    }
    {   // tile: 16 rows x 128 cols of h = gelu(x @ U_w + U_b)
        const int rt = bid / 6, ct = bid % 6;
        const int r0 = rt * 16, gc0 = ct * 128;
#pragma unroll
        for (int i = 0; i < 24; i++) {
            int e = t + i * 256;          // e < 6144
            int k = e % 384, row = e / 384;
            sm[k * K1S + row] = x[(size_t)(r0 + row) * FEAT + k];
        }
        __syncthreads();
        const int cg = t & 63, kq = t >> 6, cc = cg * 2;
        ull acc[2][8] = {};
        const float* wb = U_w + (size_t)(kq * 96) * FFN + gc0 + cc;
        for (int kb = 0; kb < 96; kb += 8) {
            float2 w[8];
#pragma unroll
            for (int i = 0; i < 8; i++)
                w[i] = *(const float2*)(wb + (size_t)(kb + i) * FFN);
#pragma unroll
            for (int i = 0; i < 8; i++) {
                int k = kq * 96 + kb + i;
                ull w0 = dup2(w[i].x), w1 = dup2(w[i].y);
                const float* xp = &sm[k * K1S];
#pragma unroll
                for (int rp = 0; rp < 8; rp++) {
                    ull xv = *(const ull*)(xp + 2 * rp);
                    fma2(acc[0][rp], w0, xv);
                    fma2(acc[1][rp], w1, xv);
                }
            }
        }
        __syncthreads();                  // staging reads done; reuse sm
#pragma unroll
        for (int rp = 0; rp < 8; rp++) {
            float2 p0 = unp2(acc[0][rp]), p1 = unp2(acc[1][rp]);
            sm[kq * 2048 + (2 * rp) * 128 + cc]         = p0.x;
            sm[kq * 2048 + (2 * rp + 1) * 128 + cc]     = p0.y;
            sm[kq * 2048 + (2 * rp) * 128 + cc + 1]     = p1.x;
            sm[kq * 2048 + (2 * rp + 1) * 128 + cc + 1] = p1.y;
        }
        __syncthreads();
#pragma unroll
        for (int i = 0; i < 8; i++) {
            int idx = t + i * 256;
            int r = idx >> 7, c = idx & 127;
            float v = sm[r * 128 + c] + sm[2048 + r * 128 + c]
                    + sm[4096 + r * 128 + c] + sm[6144 + r * 128 + c] + U_b[gc0 + c];
            v = gelu_exact(v);
            int gcol = gc0 + c;
            if (gcol < ZD) g_xh[(size_t)(r0 + r) * ZD + gcol] = v;
            else           g_z[(size_t)(r0 + r) * ZD + gcol - ZD] = v;
        }
    }
    gbar();

    // ================= phase 2: k2 LN + AE diag + dots (blocks 0..127) =====
    if (bid < 128) {
        const int r0 = bid * 4;
        float* zs2 = sm;                  // 384*6 = 2304
        float* par = sm + 2304;           // 3072
        float* hs2 = sm + 5376;           // 192*6 = 1152
#pragma unroll
        for (int i = 0; i < 6; i++) {
            int e = t + i * 256;          // e < 1536
            int r = e / 384, k = e % 384;
            zs2[k * 6 + r] = g_z[(size_t)(r0 + r) * ZD + k];
        }
        __syncthreads();
        // ---- LayerNorm (cols t and t+256) ----
        float v0[4], v1[4], s[4], q[4];
#pragma unroll
        for (int r = 0; r < 4; r++) { v0[r] = zs2[t * 6 + r]; s[r] = v0[r]; q[r] = v0[r] * v0[r]; }
        if (t < 128) {
#pragma unroll
            for (int r = 0; r < 4; r++) {
                v1[r] = zs2[(t + 256) * 6 + r];
                s[r] += v1[r]; q[r] += v1[r] * v1[r];
            }
        }
#pragma unroll
        for (int r = 0; r < 4; r++) {
#pragma unroll
            for (int o = 16; o > 0; o >>= 1) {
                s[r] += __shfl_down_sync(0xffffffffu, s[r], o);
                q[r] += __shfl_down_sync(0xffffffffu, q[r], o);
            }
            if (lane == 0) { rs1[r][wid] = s[r]; rs2[r][wid] = q[r]; }
        }
        __syncthreads();
        if (t < 4) {
            float ss = 0.f, qq = 0.f;
#pragma unroll
            for (int i = 0; i < 8; i++) { ss += rs1[t][i]; qq += rs2[t][i]; }
            float mu  = ss * (1.0f / ZD);
            float var = qq * (1.0f / ZD) - mu * mu;
            mu_s[t]  = mu;
            rsd_s[t] = rsqrtf(var + LN_EPS);
        }
        __syncthreads();
        {
            float lw = ln_w[t], lb = ln_b[t];
#pragma unroll
            for (int r = 0; r < 4; r++)
                zs2[t * 6 + r] = (v0[r] - mu_s[r]) * rsd_s[r] * lw + lb;
            if (t < 128) {
                float lw2 = ln_w[t + 256], lb2 = ln_b[t + 256];
#pragma unroll
                for (int r = 0; r < 4; r++)
                    zs2[(t + 256) * 6 + r] = (v1[r] - mu_s[r]) * rsd_s[r] * lw2 + lb2;
            }
        }
        __syncthreads();
        // ---- encoder GEMM: 64 groups x 3 cols, 4 k-slices of 96 ----
        {
            const int cg = t & 63, kq = t >> 6, cc = cg * 3;
            ull acc[3][2] = {};
            const float* wb = enc_w + (size_t)(kq * 96) * HID + cc;
            for (int kb = 0; kb < 96; kb += 8) {
                float w0[8], w1[8], w2[8];
#pragma unroll
                for (int i = 0; i < 8; i++) {
                    const float* p = wb + (size_t)(kb + i) * HID;
                    w0[i] = p[0]; w1[i] = p[1]; w2[i] = p[2];
                }
#pragma unroll
                for (int i = 0; i < 8; i++) {
                    int k = kq * 96 + kb + i;
                    const float* zp = &zs2[k * 6];
                    ull z0 = *(const ull*)zp, z1 = *(const ull*)(zp + 2);
                    ull W0 = dup2(w0[i]), W1 = dup2(w1[i]), W2 = dup2(w2[i]);
                    fma2(acc[0][0], W0, z0); fma2(acc[0][1], W0, z1);
                    fma2(acc[1][0], W1, z0); fma2(acc[1][1], W1, z1);
                    fma2(acc[2][0], W2, z0); fma2(acc[2][1], W2, z1);
                }
            }
#pragma unroll
            for (int j = 0; j < 3; j++) {
                float2 a = unp2(acc[j][0]), b2 = unp2(acc[j][1]);
                par[kq * 768 + 0 * 192 + cc + j] = a.x;
                par[kq * 768 + 1 * 192 + cc + j] = a.y;
                par[kq * 768 + 2 * 192 + cc + j] = b2.x;
                par[kq * 768 + 3 * 192 + cc + j] = b2.y;
            }
        }
        __syncthreads();
#pragma unroll
        for (int i = 0; i < 3; i++) {
            int e = t + i * 256;          // e < 768
            int r = e / 192, c = e % 192;
            float h = enc_b[c];
#pragma unroll
            for (int qq = 0; qq < 4; qq++) h += par[qq * 768 + r * 192 + c];
            hs2[c * 6 + r] = gelu_exact(h);
        }
        __syncthreads();
        // ---- decoder GEMM: 128 groups x 3 cols, 2 u-slices of 96 ----
        {
            const int cg = t & 127, kq = t >> 7, cc = cg * 3;
            ull acc[3][2] = {};
            const float* wb = dec_w + (size_t)(kq * 96) * ZD + cc;
            for (int ub = 0; ub < 96; ub += 8) {
                float w0[8], w1[8], w2[8];
#pragma unroll
                for (int i = 0; i < 8; i++) {
                    const float* p = wb + (size_t)(ub + i) * ZD;
                    w0[i] = p[0]; w1[i] = p[1]; w2[i] = p[2];
                }
#pragma unroll
                for (int i = 0; i < 8; i++) {
                    int u = kq * 96 + ub + i;
                    const float* hp = &hs2[u * 6];
                    ull h0 = *(const ull*)hp, h1 = *(const ull*)(hp + 2);
                    ull W0 = dup2(w0[i]), W1 = dup2(w1[i]), W2 = dup2(w2[i]);
                    fma2(acc[0][0], W0, h0); fma2(acc[0][1], W0, h1);
                    fma2(acc[1][0], W1, h0); fma2(acc[1][1], W1, h1);
                    fma2(acc[2][0], W2, h0); fma2(acc[2][1], W2, h1);
                }
            }
            __syncthreads();              // par reads (hs reduce) done
#pragma unroll
            for (int j = 0; j < 3; j++) {
                float2 a = unp2(acc[j][0]), b2 = unp2(acc[j][1]);
                par[kq * 1536 + 0 * 384 + cc + j] = a.x;
                par[kq * 1536 + 1 * 384 + cc + j] = a.y;
                par[kq * 1536 + 2 * 384 + cc + j] = b2.x;
                par[kq * 1536 + 3 * 384 + cc + j] = b2.y;
            }
        }
        __syncthreads();
        // ---- reduce + dots ----
        float d[4] = {0.f, 0.f, 0.f, 0.f}, o[4] = {0.f, 0.f, 0.f, 0.f};
#pragma unroll
        for (int ci = 0; ci < 2; ci++) {
            int c = t + ci * 256;
            if (c < 384) {
                float db = dec_b[c], c0f = g_c0[c];
#pragma unroll
                for (int r = 0; r < 4; r++) {
                    float p  = par[r * 384 + c] + par[1536 + r * 384 + c] + db;
                    float zv = zs2[c * 6 + r];
                    d[r] += p * zv;
                    o[r] += c0f * zv;
                }
            }
        }
#pragma unroll
        for (int r = 0; r < 4; r++) {
#pragma unroll
            for (int ss = 16; ss > 0; ss >>= 1) {
                d[r] += __shfl_down_sync(0xffffffffu, d[r], ss);
                o[r] += __shfl_down_sync(0xffffffffu, o[r], ss);
            }
            if (lane == 0) { redd[r][wid] = d[r]; redo[r][wid] = o[r]; }
        }
        __syncthreads();
        if (t < 4) {
            float dd = 0.f, oo = 0.f;
#pragma unroll
            for (int i = 0; i < 8; i++) { dd += redd[t][i]; oo += redo[t][i]; }
            g_diag[r0 + t] = dd;
            g_off[r0 + t]  = oo;
        }
    }
    gbar();

    // ================= phase 3: softmax stats + T (blocks 0..3) ============
    if (bid < NB) {
        const int b = bid;
        float off = 0.f, dg = 0.f, a = 0.f, wdv = 0.f;
        if (t < NN) {
            off = g_off[b * NN + t];
            dg  = g_diag[b * NN + t];
            float m = fmaxf(off, dg);
#pragma unroll
            for (int s = 16; s > 0; s >>= 1) m = fmaxf(m, __shfl_down_sync(0xffffffffu, m, s));
            if (lane == 0) red[wid] = m;
        }
        __syncthreads();
        if (t == 0) red[4] = fmaxf(fmaxf(red[0], red[1]), fmaxf(red[2], red[3]));
        __syncthreads();
        if (t < NN) {
            float m = red[4];
            a = expf(off - m);
            float c = expf(dg - m);
            eo_s[t] = a;
            wdv = c - a;
            float e1 = a;
#pragma unroll
            for (int s = 16; s > 0; s >>= 1) e1 += __shfl_down_sync(0xffffffffu, e1, s);
            if (lane == 0) red[wid] = e1;
        }
        __syncthreads();
        if (t == 0) red[4] = red[0] + red[1] + red[2] + red[3];
        __syncthreads();
        if (t < NN) {
            float S = red[4];
            g_eo[b * NN + t] = a;
            g_wd[b * NN + t] = wdv;
            g_rD[b * NN + t] = 1.0f / (S + wdv);
        }
        __syncthreads();
        // T[c] = sum_j eo[j] * xh[b,j,c]
#pragma unroll
        for (int ci = 0; ci < 2; ci++) {
            int c = t + ci * 256;
            if (c < 384) {
                float T = 0.f;
                const float* xh = g_xh + (size_t)b * NN * ZD + c;
                for (int jb = 0; jb < NN; jb += 16) {
                    float xv[16];
#pragma unroll
                    for (int i = 0; i < 16; i++) xv[i] = xh[(size_t)(jb + i) * ZD];
#pragma unroll
                    for (int i = 0; i < 16; i++) T += eo_s[jb + i] * xv[i];
                }
                g_T[b * ZD + c] = T;
            }
        }
    }
    gbar();

    // ================= phase 4: k4 combine + final GEMM (all blocks) =======
    {
        const int rt = bid / 3, ct = bid % 3;
        const int r0 = rt * 8, c0 = ct * 128;
        const int b  = r0 / NN;
        if (t < 8) { wds[t] = g_wd[r0 + t]; rds[t] = g_rD[r0 + t]; }
        __syncthreads();
#pragma unroll
        for (int i = 0; i < 12; i++) {
            int e = t + i * 256;          // e < 3072
            int r = e / 384, f = e % 384;
            sm[f * K4S + r] = (g_T[b * ZD + f] + wds[r] * g_xh[(size_t)(r0 + r) * ZD + f]) * rds[r];
        }
        __syncthreads();
        const int cg = t & 63, kq = t >> 6, cc = cg * 2;
        ull acc[2][4] = {};
        const float* wb = V_w + (size_t)(kq * 96) * FEAT + c0 + cc;
        for (int fb = 0; fb < 96; fb += 8) {
            float2 w[8];
#pragma unroll
            for (int i = 0; i < 8; i++)
                w[i] = *(const float2*)(wb + (size_t)(fb + i) * FEAT);
#pragma unroll
            for (int i = 0; i < 8; i++) {
                int f = kq * 96 + fb + i;
                ull w0 = dup2(w[i].x), w1 = dup2(w[i].y);
                const float* up = &sm[f * K4S];
#pragma unroll
                for (int rp = 0; rp < 4; rp++) {
                    ull uv = *(const ull*)(up + 2 * rp);
                    fma2(acc[0][rp], w0, uv);
                    fma2(acc[1][rp], w1, uv);
                }
            }
        }
        __syncthreads();                  // staging reads done; reuse sm
#pragma unroll
        for (int rp = 0; rp < 4; rp++) {
            float2 p0 = unp2(acc[0][rp]), p1 = unp2(acc[1][rp]);
            sm[kq * 1024 + (2 * rp) * 128 + cc]         = p0.x;
            sm[kq * 1024 + (2 * rp + 1) * 128 + cc]     = p0.y;
            sm[kq * 1024 + (2 * rp) * 128 + cc + 1]     = p1.x;
            sm[kq * 1024 + (2 * rp + 1) * 128 + cc + 1] = p1.y;
        }
        __syncthreads();
#pragma unroll
        for (int i = 0; i < 4; i++) {
            int idx = t + i * 256;
            int r = idx >> 7, c = idx & 127;
            out[(size_t)(r0 + r) * FEAT + c0 + c] =
                sm[r * 128 + c] + sm[1024 + r * 128 + c]
              + sm[2048 + r * 128 + c] + sm[3072 + r * 128 + c] + V_b[c0 + c];
        }
    }
}

// ---------------- launch ---------------------------------------------------
extern "C" void kernel_launch(void* const* d_in, const int* in_sizes, int n_in,
                              void* d_out, int out_size) {
    const float* x     = (const float*)d_in[0];
    const float* U_w   = (const float*)d_in[1];
    const float* U_b   = (const float*)d_in[2];
    const float* ln_w  = (const float*)d_in[3];
    const float* ln_b  = (const float*)d_in[4];
    const float* enc_w = (const float*)d_in[5];
    const float* enc_b = (const float*)d_in[6];
    const float* dec_w = (const float*)d_in[7];
    const float* dec_b = (const float*)d_in[8];
    const float* V_w   = (const float*)d_in[9];
    const float* V_b   = (const float*)d_in[10];
    float* out = (float*)d_out;

    fused_all<<<NBLK, 256>>>(x, U_w, U_b, ln_w, ln_b, enc_w, enc_b,
                             dec_w, dec_b, V_w, V_b, out);
}